// round 15
// baseline (speedup 1.0000x reference)
#include <cuda_runtime.h>

// SurfEval: NURBS surface evaluation. B=8, M=N=64, P=Q=3, GRID=512, DIM=3.
// Inputs: ctrl_pts [B,M,N,4], uspan [G], vspan [G], Nu [G,4], Nv [G,4]
// Output: float32 [B, G, G, 3]
//
// R11 design (resubmit #4; broker timeouts R11-R14):
//      R10 (15.1us) showed nothing saturated (L1 53%, issue 31%) ->
//      issue-efficiency x instruction-count bound. Cut instructions:
//      - direct interleaved stores (no 24KB staging, no 2nd barrier)
//      - float4-vectorized Phase-1 (4 LDG.128 instead of 16 LDG.32 chains)
//      Keep: interleaved PPT mapping (broadcast LDS), batched reciprocal.

#define BB    8
#define MM    64
#define NN    64
#define GRIDD 512
#define RPC   4          // rows (g values) per CTA
#define PPT   4          // points per thread, stride 128

__global__ __launch_bounds__(512)
void surf_eval_kernel(const float* __restrict__ ctrl,
                      const int*   __restrict__ uspan,
                      const int*   __restrict__ vspan,
                      const float* __restrict__ Nu,
                      const float* __restrict__ Nv,
                      float*       __restrict__ out)
{
    __shared__ float su_s[RPC * NN * 4];        // 4 KB: Su for 4 rows

    const int g0 = blockIdx.x * RPC;
    const int b  = blockIdx.y;
    const int t  = threadIdx.x;                 // 0..511

    const int irow = t >> 7;                    // 0..3: which row
    const int i    = t & 127;                   // lane-group index within row

    // ---- Hoisted Phase-2 operands (latency overlaps Phase 1) ----
    int    sv[PPT];
    float4 nv[PPT];
    #pragma unroll
    for (int p = 0; p < PPT; p++) {
        const int h = i + 128 * p;              // interleaved: lanes consecutive
        sv[p] = vspan[h];
        nv[p] = *reinterpret_cast<const float4*>(Nv + 4 * h);
    }

    // ---- Phase 1: vectorized u-contraction, 4 rows into shared memory ----
    // 4 rows x 64 float4-slots = 256 float4; threads 0..255, one each.
    if (t < RPC * NN) {
        const int row = t >> 6;                 // 0..3
        const int j4  = t & 63;                 // float4 index within row
        const int    su = uspan[g0 + row];
        const float4 nu = *reinterpret_cast<const float4*>(Nu + 4 * (g0 + row));
        const float4* base = reinterpret_cast<const float4*>(
            ctrl + ((size_t)b * MM + (su - 3)) * (NN * 4));
        const float4 r0 = base[j4];
        const float4 r1 = base[j4 + NN];
        const float4 r2 = base[j4 + 2 * NN];
        const float4 r3 = base[j4 + 3 * NN];
        float4 acc;
        acc.x = nu.x * r0.x + nu.y * r1.x + nu.z * r2.x + nu.w * r3.x;
        acc.y = nu.x * r0.y + nu.y * r1.y + nu.z * r2.y + nu.w * r3.y;
        acc.z = nu.x * r0.z + nu.y * r1.z + nu.z * r2.z + nu.w * r3.z;
        acc.w = nu.x * r0.w + nu.y * r1.w + nu.z * r2.w + nu.w * r3.w;
        reinterpret_cast<float4*>(su_s)[t] = acc;
    }
    __syncthreads();

    // ---- Phase 2: v-contraction, 4 interleaved points per thread ----
    const float* su_row = su_s + irow * (NN * 4);

    float xr[PPT], yr[PPT], zr[PPT], wr[PPT];
    #pragma unroll
    for (int p = 0; p < PPT; p++) {
        const int s = sv[p];
        const float4 p0 = *reinterpret_cast<const float4*>(su_row + 4 * (s - 3));
        const float4 p1 = *reinterpret_cast<const float4*>(su_row + 4 * (s - 2));
        const float4 p2 = *reinterpret_cast<const float4*>(su_row + 4 * (s - 1));
        const float4 p3 = *reinterpret_cast<const float4*>(su_row + 4 * (s - 0));
        const float4 c  = nv[p];

        xr[p] = c.x * p0.x + c.y * p1.x + c.z * p2.x + c.w * p3.x;
        yr[p] = c.x * p0.y + c.y * p1.y + c.z * p2.y + c.w * p3.y;
        zr[p] = c.x * p0.z + c.y * p1.z + c.z * p2.z + c.w * p3.z;
        wr[p] = c.x * p0.w + c.y * p1.w + c.z * p2.w + c.w * p3.w;
    }

    // ---- Batched reciprocal: 1 MUFU.RCP per 4 points ----
    const float P01 = wr[0] * wr[1];
    const float P23 = wr[2] * wr[3];
    const float P   = P01 * P23;
    float r;
    asm("rcp.approx.f32 %0, %1;" : "=f"(r) : "f"(P));
    r = r * (2.0f - P * r);                     // Newton step on FMA pipe

    float inv[PPT];
    inv[0] = r * wr[1] * P23;
    inv[1] = r * wr[0] * P23;
    inv[2] = r * P01 * wr[3];
    inv[3] = r * P01 * wr[2];

    // ---- Direct stores: 12 STG.32; warp footprint 384 contiguous bytes ----
    float* orow = out + ((size_t)b * GRIDD + (g0 + irow)) * GRIDD * 3;
    #pragma unroll
    for (int p = 0; p < PPT; p++) {
        const int h = i + 128 * p;
        orow[h * 3 + 0] = xr[p] * inv[p];
        orow[h * 3 + 1] = yr[p] * inv[p];
        orow[h * 3 + 2] = zr[p] * inv[p];
    }
}

extern "C" void kernel_launch(void* const* d_in, const int* in_sizes, int n_in,
                              void* d_out, int out_size)
{
    const float* ctrl  = (const float*)d_in[0];
    const int*   uspan = (const int*)  d_in[1];
    const int*   vspan = (const int*)  d_in[2];
    const float* Nu    = (const float*)d_in[3];
    const float* Nv    = (const float*)d_in[4];
    float*       out   = (float*)d_out;

    dim3 grid(GRIDD / RPC, BB);   // 128 x 8 = 1024 CTAs
    surf_eval_kernel<<<grid, 512>>>(ctrl, uspan, vspan, Nu, Nv, out);
}